// round 6
// baseline (speedup 1.0000x reference)
#include <cuda_runtime.h>
#include <math.h>

// Problem constants (fixed by the reference setup_inputs)
#define Bb 2
#define Tt 12
#define Nn 4096
#define Kk 16
#define Hh 4
#define Cc 16
#define Vv 3

#define BTNH (Bb*Tt*Nn*Hh)                  // 393216
#define U_SIZE ((size_t)Bb*Tt*Nn*Kk*Hh)     // 6291456
#define BRNH (Bb*(Tt-1)*Nn*Hh)              // 360448

#define SZ_FEATURES 6291456
#define SZ_MULTIQ   3072
#define SZ_MULTIM   1024
#define SZ_NEAREST  69632

#define FLT_MIN_NORMAL 1.17549435e-38f

// FTZ emulation: flush subnormal results to zero
__device__ __forceinline__ float ftz(float x) {
    return (fabsf(x) < FLT_MIN_NORMAL) ? 0.f : x;
}

// Scratch
__device__ float g_buf[(size_t)BTNH * Cc];
__device__ float deg_buf[BTNH];

// ---------------------------------------------------------------------------
// K1: g = multiM @ f  (M = 2I exactly -> bit-exact restructuring)
// ---------------------------------------------------------------------------
__global__ void k1_compute_g(const float* __restrict__ f,
                             const float* __restrict__ M)
{
    __shared__ float sM[Hh * Cc * Cc];
    for (int i = threadIdx.x; i < Hh * Cc * Cc; i += blockDim.x) sM[i] = M[i];
    __syncthreads();

    int idx = blockIdx.x * blockDim.x + threadIdx.x;
    if (idx >= BTNH) return;
    int h = idx & (Hh - 1);

    const float* fv = f + (size_t)idx * Cc;
    float x[Cc];
#pragma unroll
    for (int c = 0; c < Cc; c += 4) {
        float4 t = *reinterpret_cast<const float4*>(fv + c);
        x[c] = t.x; x[c+1] = t.y; x[c+2] = t.z; x[c+3] = t.w;
    }

    const float* Mh = sM + h * Cc * Cc;
    float y[Cc];
#pragma unroll
    for (int i = 0; i < Cc; i++) {
        float s = 0.f;
#pragma unroll
        for (int j = 0; j < Cc; j++) s = __fadd_rn(s, __fmul_rn(Mh[i * Cc + j], x[j]));
        y[i] = s;
    }

    float* gv = g_buf + (size_t)idx * Cc;
#pragma unroll
    for (int c = 0; c < Cc; c += 4) {
        float4 t; t.x = y[c]; t.y = y[c+1]; t.z = y[c+2]; t.w = y[c+3];
        *reinterpret_cast<float4*>(gv + c) = t;
    }
}

// ---------------------------------------------------------------------------
// K2: w_k = ftz(expf(-||g_i - g_j||^2)); deg = sum_k w_k
// ---------------------------------------------------------------------------
__global__ void k2_w_deg(const int* __restrict__ nn,
                         float* __restrict__ out_u)
{
    int idx = blockIdx.x * blockDim.x + threadIdx.x;
    if (idx >= BTNH) return;
    int h  = idx & (Hh - 1);
    int n  = (idx >> 2) & (Nn - 1);
    int bt = idx >> 14;

    float gi[Cc];
    const float* gvi = g_buf + (size_t)idx * Cc;
#pragma unroll
    for (int c = 0; c < Cc; c += 4) {
        float4 t = *reinterpret_cast<const float4*>(gvi + c);
        gi[c] = t.x; gi[c+1] = t.y; gi[c+2] = t.z; gi[c+3] = t.w;
    }

    const float* gbase = g_buf + (size_t)bt * Nn * Hh * Cc;
    const int*   nrow  = nn + n * (Kk + 1) + 1;
    float* ubase = out_u + (((size_t)bt * Nn + n) * Kk) * Hh + h;

    float deg = 0.f;
#pragma unroll 4
    for (int k = 0; k < Kk; k++) {
        int j = nrow[k];
        float w = 0.f;
        if (j >= 0) {
            const float* gj = gbase + ((size_t)j * Hh + h) * Cc;
            float s = 0.f;
#pragma unroll
            for (int c = 0; c < Cc; c += 4) {
                float4 t = *reinterpret_cast<const float4*>(gj + c);
                float d0 = __fsub_rn(gi[c],   t.x);
                float d1 = __fsub_rn(gi[c+1], t.y);
                float d2 = __fsub_rn(gi[c+2], t.z);
                float d3 = __fsub_rn(gi[c+3], t.w);
                s = __fadd_rn(s, __fmul_rn(d0, d0));
                s = __fadd_rn(s, __fmul_rn(d1, d1));
                s = __fadd_rn(s, __fmul_rn(d2, d2));
                s = __fadd_rn(s, __fmul_rn(d3, d3));
            }
            w = ftz(expf(-s));       // FTZ on exp result
        }
        deg = __fadd_rn(deg, w);
        ubase[(size_t)k * Hh] = w;
    }
    deg_buf[idx] = deg;
}

// ---------------------------------------------------------------------------
// K3: FTZ on the deg_i*deg_j product (kills denormal-product monsters),
//     then u_w *= inv_dm with FTZ on the final product.
// ---------------------------------------------------------------------------
__global__ void k3_normalize(const int* __restrict__ nn,
                             float* __restrict__ out_u)
{
    int idx = blockIdx.x * blockDim.x + threadIdx.x;
    if (idx >= BTNH) return;
    int h  = idx & (Hh - 1);
    int n  = (idx >> 2) & (Nn - 1);
    int bt = idx >> 14;

    float degi = deg_buf[idx];
    const float* dbase = deg_buf + (size_t)bt * Nn * Hh;
    const int*   nrow  = nn + n * (Kk + 1) + 1;
    float* ubase = out_u + (((size_t)bt * Nn + n) * Kk) * Hh + h;

#pragma unroll 4
    for (int k = 0; k < Kk; k++) {
        int j  = nrow[k];
        int jj = j % Nn; if (jj < 0) jj += Nn;
        float degj = dbase[(size_t)jj * Hh + h];
        float P    = ftz(__fmul_rn(degi, degj));   // FTZ: denormal product -> 0
        float dm   = sqrtf(P);
        float inv  = (dm > 0.f) ? __fdiv_rn(1.f, dm) : 0.f;
        float u    = ftz(__fmul_rn(ubase[(size_t)k * Hh], inv));
        ubase[(size_t)k * Hh] = u;
    }
}

// ---------------------------------------------------------------------------
// K4: temporal path (O(1) values; FTZ irrelevant there)
// ---------------------------------------------------------------------------
__global__ void k4_temporal(const float* __restrict__ f,
                            const float* __restrict__ Q,
                            float* __restrict__ out_d)
{
    __shared__ float sQ[Vv * Hh * Cc * Cc];
    for (int i = threadIdx.x; i < Vv * Hh * Cc * Cc; i += blockDim.x) sQ[i] = Q[i];
    __syncthreads();

    int idx = blockIdx.x * blockDim.x + threadIdx.x;
    if (idx >= BRNH) return;
    int h  = idx & (Hh - 1);
    int n  = (idx >> 2) & (Nn - 1);
    int br = idx >> 14;
    int r  = br % (Tt - 1);
    int b  = br / (Tt - 1);
    int tcur = r + 1;

    const float* fb = f + (size_t)b * Tt * Nn * Hh * Cc;
    const float* fc = fb + (((size_t)tcur * Nn + n) * Hh + h) * Cc;

    float xc[Cc];
#pragma unroll
    for (int c = 0; c < Cc; c += 4) {
        float4 t = *reinterpret_cast<const float4*>(fc + c);
        xc[c] = t.x; xc[c+1] = t.y; xc[c+2] = t.z; xc[c+3] = t.w;
    }

    float wd[Vv];
    float indeg = 0.f;
#pragma unroll
    for (int v = 0; v < Vv; v++) {
        float w = 0.f;
        if (v <= r) {
            int tp = r - v;
            const float* fp = fb + (((size_t)tp * Nn + n) * Hh + h) * Cc;
            float d[Cc];
#pragma unroll
            for (int c = 0; c < Cc; c += 4) {
                float4 t = *reinterpret_cast<const float4*>(fp + c);
                d[c]   = __fsub_rn(t.x, xc[c]);
                d[c+1] = __fsub_rn(t.y, xc[c+1]);
                d[c+2] = __fsub_rn(t.z, xc[c+2]);
                d[c+3] = __fsub_rn(t.w, xc[c+3]);
            }
            const float* Qh = sQ + (v * Hh + h) * Cc * Cc;
#pragma unroll
            for (int i = 0; i < Cc; i++) {
                float a = 0.f;
#pragma unroll
                for (int j = 0; j < Cc; j++) a = __fadd_rn(a, __fmul_rn(Qh[i * Cc + j], d[j]));
                float e = expf(-__fmul_rn(a, a));
                w = __fadd_rn(w, e);
            }
        }
        wd[v] = w;
        indeg = __fadd_rn(indeg, w);
    }
    float inv = (indeg > 0.f) ? __fdiv_rn(1.f, indeg) : 0.f;

    size_t obase = ((size_t)(b * (Tt - 1) + r)) * Vv * Nn * Hh + (size_t)n * Hh + h;
#pragma unroll
    for (int v = 0; v < Vv; v++)
        out_d[obase + (size_t)v * Nn * Hh] = __fmul_rn(wd[v], inv);
}

// ---------------------------------------------------------------------------
extern "C" void kernel_launch(void* const* d_in, const int* in_sizes, int n_in,
                              void* d_out, int out_size)
{
    const float* features = nullptr;
    const float* multiQ   = nullptr;
    const float* multiM   = nullptr;
    const int*   nearest  = nullptr;
    for (int i = 0; i < n_in; i++) {
        switch (in_sizes[i]) {
            case SZ_FEATURES: features = (const float*)d_in[i]; break;
            case SZ_MULTIQ:   multiQ   = (const float*)d_in[i]; break;
            case SZ_MULTIM:   multiM   = (const float*)d_in[i]; break;
            case SZ_NEAREST:  nearest  = (const int*)  d_in[i]; break;
            default: break;
        }
    }

    float* out_u = (float*)d_out;
    float* out_d = (float*)d_out + U_SIZE;

    {
        int threads = 256, blocks = (BTNH + threads - 1) / threads;
        k1_compute_g<<<blocks, threads>>>(features, multiM);
    }
    {
        int threads = 128, blocks = (BTNH + threads - 1) / threads;
        k2_w_deg<<<blocks, threads>>>(nearest, out_u);
    }
    {
        int threads = 128, blocks = (BTNH + threads - 1) / threads;
        k3_normalize<<<blocks, threads>>>(nearest, out_u);
    }
    {
        int threads = 256, blocks = (BRNH + threads - 1) / threads;
        k4_temporal<<<blocks, threads>>>(features, multiQ, out_d);
    }
}

// round 8
// speedup vs baseline: 2.2933x; 2.2933x over previous
#include <cuda_runtime.h>
#include <math.h>

// Problem constants (fixed by the reference setup_inputs)
#define Bb 2
#define Tt 12
#define Nn 4096
#define Kk 16
#define Hh 4
#define Cc 16
#define Vv 3

#define BTNH (Bb*Tt*Nn*Hh)                  // 393216
#define U_SIZE ((size_t)Bb*Tt*Nn*Kk*Hh)     // 6291456
#define BRNH (Bb*(Tt-1)*Nn*Hh)              // 360448

#define SZ_FEATURES 6291456
#define SZ_MULTIQ   3072
#define SZ_MULTIM   1024
#define SZ_NEAREST  69632

#define FLT_MIN_NORMAL 1.17549435e-38f

// FTZ emulation: flush subnormal results to zero (reference pipeline semantics)
__device__ __forceinline__ float ftz(float x) {
    return (fabsf(x) < FLT_MIN_NORMAL) ? 0.f : x;
}

// Scratch / analysis results (static device memory — no runtime allocation)
__device__ float g_buf[(size_t)BTNH * Cc];   // only used by general fallback
__device__ float deg_buf[BTNH];
__device__ int   d_diag_flags[2];            // [0]=multiM diagonal, [1]=multiQ diagonal
__device__ float d_Mdiag[Hh * Cc];
__device__ float d_Qdiag[Vv * Hh * Cc];

// ---------------------------------------------------------------------------
// K0: analyze multiM / multiQ. Diagonal matrices admit a bit-exact fast path
// (matvec has exactly one nonzero term; adding exact zeros is identity).
// ---------------------------------------------------------------------------
__global__ void k0_analyze(const float* __restrict__ M,
                           const float* __restrict__ Q)
{
    __shared__ int okM, okQ;
    if (threadIdx.x == 0) { okM = 1; okQ = 1; }
    __syncthreads();

    for (int i = threadIdx.x; i < Hh * Cc * Cc; i += blockDim.x) {
        int r = (i / Cc) % Cc, c = i % Cc;
        float v = M[i];
        if (r != c && v != 0.f) atomicAnd(&okM, 0);
        if (r == c) d_Mdiag[(i / (Cc * Cc)) * Cc + r] = v;
    }
    for (int i = threadIdx.x; i < Vv * Hh * Cc * Cc; i += blockDim.x) {
        int r = (i / Cc) % Cc, c = i % Cc;
        float v = Q[i];
        if (r != c && v != 0.f) atomicAnd(&okQ, 0);
        if (r == c) d_Qdiag[(i / (Cc * Cc)) * Cc + r] = v;
    }
    __syncthreads();
    if (threadIdx.x == 0) { d_diag_flags[0] = okM; d_diag_flags[1] = okQ; }
}

// ---------------------------------------------------------------------------
// K1 (fallback only): g = multiM @ f. Skipped when multiM is diagonal.
// ---------------------------------------------------------------------------
__global__ void k1_compute_g(const float* __restrict__ f,
                             const float* __restrict__ M)
{
    if (d_diag_flags[0]) return;   // fast path doesn't need g_buf

    __shared__ float sM[Hh * Cc * Cc];
    for (int i = threadIdx.x; i < Hh * Cc * Cc; i += blockDim.x) sM[i] = M[i];
    __syncthreads();

    int idx = blockIdx.x * blockDim.x + threadIdx.x;
    if (idx >= BTNH) return;
    int h = idx & (Hh - 1);

    const float* fv = f + (size_t)idx * Cc;
    float x[Cc];
#pragma unroll
    for (int c = 0; c < Cc; c += 4) {
        float4 t = *reinterpret_cast<const float4*>(fv + c);
        x[c] = t.x; x[c+1] = t.y; x[c+2] = t.z; x[c+3] = t.w;
    }
    const float* Mh = sM + h * Cc * Cc;
    float y[Cc];
#pragma unroll
    for (int i = 0; i < Cc; i++) {
        float s = 0.f;
#pragma unroll
        for (int j = 0; j < Cc; j++) s = __fadd_rn(s, __fmul_rn(Mh[i * Cc + j], x[j]));
        y[i] = s;
    }
    float* gv = g_buf + (size_t)idx * Cc;
#pragma unroll
    for (int c = 0; c < Cc; c += 4) {
        float4 t; t.x = y[c]; t.y = y[c+1]; t.z = y[c+2]; t.w = y[c+3];
        *reinterpret_cast<float4*>(gv + c) = t;
    }
}

// ---------------------------------------------------------------------------
// K2: w_k = ftz(expf(-sum_i (M df)_i^2)); deg = sum_k w_k
// Diagonal fast path: (M df)_i = m_i * (f_i - f_j)_i, bit-exact vs reference.
// ---------------------------------------------------------------------------
__global__ void k2_w_deg(const float* __restrict__ f,
                         const int* __restrict__ nn,
                         float* __restrict__ out_u)
{
    __shared__ float sm[Hh * Cc];
    for (int i = threadIdx.x; i < Hh * Cc; i += blockDim.x) sm[i] = d_Mdiag[i];
    __syncthreads();

    int idx = blockIdx.x * blockDim.x + threadIdx.x;
    if (idx >= BTNH) return;
    int h  = idx & (Hh - 1);
    int n  = (idx >> 2) & (Nn - 1);
    int bt = idx >> 14;

    const int*   nrow  = nn + n * (Kk + 1) + 1;   // skip self column
    float* ubase = out_u + (((size_t)bt * Nn + n) * Kk) * Hh + h;

    int diag = d_diag_flags[0];
    float deg = 0.f;

    if (diag) {
        // ---- fast path: read features directly, diagonal M ----
        const float* fvi = f + (size_t)idx * Cc;
        float fi[Cc], mv[Cc];
#pragma unroll
        for (int c = 0; c < Cc; c += 4) {
            float4 t = *reinterpret_cast<const float4*>(fvi + c);
            fi[c] = t.x; fi[c+1] = t.y; fi[c+2] = t.z; fi[c+3] = t.w;
        }
#pragma unroll
        for (int c = 0; c < Cc; c++) mv[c] = sm[h * Cc + c];

        const float* fbase = f + (size_t)bt * Nn * Hh * Cc;
#pragma unroll 4
        for (int k = 0; k < Kk; k++) {
            int j = nrow[k];
            float w = 0.f;
            if (j >= 0) {
                const float* fj = fbase + ((size_t)j * Hh + h) * Cc;
                float s = 0.f;
#pragma unroll
                for (int c = 0; c < Cc; c += 4) {
                    float4 t = *reinterpret_cast<const float4*>(fj + c);
                    float a0 = __fmul_rn(mv[c],   __fsub_rn(fi[c],   t.x));
                    float a1 = __fmul_rn(mv[c+1], __fsub_rn(fi[c+1], t.y));
                    float a2 = __fmul_rn(mv[c+2], __fsub_rn(fi[c+2], t.z));
                    float a3 = __fmul_rn(mv[c+3], __fsub_rn(fi[c+3], t.w));
                    s = __fadd_rn(s, __fmul_rn(a0, a0));
                    s = __fadd_rn(s, __fmul_rn(a1, a1));
                    s = __fadd_rn(s, __fmul_rn(a2, a2));
                    s = __fadd_rn(s, __fmul_rn(a3, a3));
                }
                w = ftz(expf(-s));
            }
            deg = __fadd_rn(deg, w);
            ubase[(size_t)k * Hh] = w;
        }
    } else {
        // ---- general fallback: use precomputed g = M f ----
        float gi[Cc];
        const float* gvi = g_buf + (size_t)idx * Cc;
#pragma unroll
        for (int c = 0; c < Cc; c += 4) {
            float4 t = *reinterpret_cast<const float4*>(gvi + c);
            gi[c] = t.x; gi[c+1] = t.y; gi[c+2] = t.z; gi[c+3] = t.w;
        }
        const float* gbase = g_buf + (size_t)bt * Nn * Hh * Cc;
#pragma unroll 4
        for (int k = 0; k < Kk; k++) {
            int j = nrow[k];
            float w = 0.f;
            if (j >= 0) {
                const float* gj = gbase + ((size_t)j * Hh + h) * Cc;
                float s = 0.f;
#pragma unroll
                for (int c = 0; c < Cc; c += 4) {
                    float4 t = *reinterpret_cast<const float4*>(gj + c);
                    float d0 = __fsub_rn(gi[c],   t.x);
                    float d1 = __fsub_rn(gi[c+1], t.y);
                    float d2 = __fsub_rn(gi[c+2], t.z);
                    float d3 = __fsub_rn(gi[c+3], t.w);
                    s = __fadd_rn(s, __fmul_rn(d0, d0));
                    s = __fadd_rn(s, __fmul_rn(d1, d1));
                    s = __fadd_rn(s, __fmul_rn(d2, d2));
                    s = __fadd_rn(s, __fmul_rn(d3, d3));
                }
                w = ftz(expf(-s));
            }
            deg = __fadd_rn(deg, w);
            ubase[(size_t)k * Hh] = w;
        }
    }
    deg_buf[idx] = deg;
}

// ---------------------------------------------------------------------------
// K3: FTZ on deg_i*deg_j product, then u_w *= inv_dm (FTZ final product)
// ---------------------------------------------------------------------------
__global__ void k3_normalize(const int* __restrict__ nn,
                             float* __restrict__ out_u)
{
    int idx = blockIdx.x * blockDim.x + threadIdx.x;
    if (idx >= BTNH) return;
    int h  = idx & (Hh - 1);
    int n  = (idx >> 2) & (Nn - 1);
    int bt = idx >> 14;

    float degi = deg_buf[idx];
    const float* dbase = deg_buf + (size_t)bt * Nn * Hh;
    const int*   nrow  = nn + n * (Kk + 1) + 1;
    float* ubase = out_u + (((size_t)bt * Nn + n) * Kk) * Hh + h;

#pragma unroll 4
    for (int k = 0; k < Kk; k++) {
        int j  = nrow[k];
        int jj = j % Nn; if (jj < 0) jj += Nn;
        float degj = dbase[(size_t)jj * Hh + h];
        float P    = ftz(__fmul_rn(degi, degj));
        float dm   = sqrtf(P);
        float inv  = (dm > 0.f) ? __fdiv_rn(1.f, dm) : 0.f;
        ubase[(size_t)k * Hh] = ftz(__fmul_rn(ubase[(size_t)k * Hh], inv));
    }
}

// ---------------------------------------------------------------------------
// K4: temporal path. Diagonal fast path: (Q_v d)_i = q_{v,h,i} * d_i.
// ---------------------------------------------------------------------------
__global__ void k4_temporal(const float* __restrict__ f,
                            const float* __restrict__ Q,
                            float* __restrict__ out_d)
{
    __shared__ float sQ[Vv * Hh * Cc * Cc];   // general fallback
    __shared__ float sQd[Vv * Hh * Cc];       // diagonal fast path
    int diag = d_diag_flags[1];
    if (diag) {
        for (int i = threadIdx.x; i < Vv * Hh * Cc; i += blockDim.x) sQd[i] = d_Qdiag[i];
    } else {
        for (int i = threadIdx.x; i < Vv * Hh * Cc * Cc; i += blockDim.x) sQ[i] = Q[i];
    }
    __syncthreads();

    int idx = blockIdx.x * blockDim.x + threadIdx.x;
    if (idx >= BRNH) return;
    int h  = idx & (Hh - 1);
    int n  = (idx >> 2) & (Nn - 1);
    int br = idx >> 14;
    int r  = br % (Tt - 1);
    int b  = br / (Tt - 1);
    int tcur = r + 1;

    const float* fb = f + (size_t)b * Tt * Nn * Hh * Cc;
    const float* fc = fb + (((size_t)tcur * Nn + n) * Hh + h) * Cc;

    float xc[Cc];
#pragma unroll
    for (int c = 0; c < Cc; c += 4) {
        float4 t = *reinterpret_cast<const float4*>(fc + c);
        xc[c] = t.x; xc[c+1] = t.y; xc[c+2] = t.z; xc[c+3] = t.w;
    }

    float wd[Vv];
    float indeg = 0.f;
#pragma unroll
    for (int v = 0; v < Vv; v++) {
        float w = 0.f;
        if (v <= r) {
            int tp = r - v;
            const float* fp = fb + (((size_t)tp * Nn + n) * Hh + h) * Cc;
            float d[Cc];
#pragma unroll
            for (int c = 0; c < Cc; c += 4) {
                float4 t = *reinterpret_cast<const float4*>(fp + c);
                d[c]   = __fsub_rn(t.x, xc[c]);
                d[c+1] = __fsub_rn(t.y, xc[c+1]);
                d[c+2] = __fsub_rn(t.z, xc[c+2]);
                d[c+3] = __fsub_rn(t.w, xc[c+3]);
            }
            if (diag) {
                const float* qv = sQd + (v * Hh + h) * Cc;
#pragma unroll
                for (int i = 0; i < Cc; i++) {
                    float a = __fmul_rn(qv[i], d[i]);   // bit-exact vs full matvec
                    float e = expf(-__fmul_rn(a, a));
                    w = __fadd_rn(w, e);
                }
            } else {
                const float* Qh = sQ + (v * Hh + h) * Cc * Cc;
#pragma unroll
                for (int i = 0; i < Cc; i++) {
                    float a = 0.f;
#pragma unroll
                    for (int j = 0; j < Cc; j++) a = __fadd_rn(a, __fmul_rn(Qh[i * Cc + j], d[j]));
                    float e = expf(-__fmul_rn(a, a));
                    w = __fadd_rn(w, e);
                }
            }
        }
        wd[v] = w;
        indeg = __fadd_rn(indeg, w);
    }
    float inv = (indeg > 0.f) ? __fdiv_rn(1.f, indeg) : 0.f;

    size_t obase = ((size_t)(b * (Tt - 1) + r)) * Vv * Nn * Hh + (size_t)n * Hh + h;
#pragma unroll
    for (int v = 0; v < Vv; v++)
        out_d[obase + (size_t)v * Nn * Hh] = __fmul_rn(wd[v], inv);
}

// ---------------------------------------------------------------------------
extern "C" void kernel_launch(void* const* d_in, const int* in_sizes, int n_in,
                              void* d_out, int out_size)
{
    const float* features = nullptr;
    const float* multiQ   = nullptr;
    const float* multiM   = nullptr;
    const int*   nearest  = nullptr;
    for (int i = 0; i < n_in; i++) {
        switch (in_sizes[i]) {
            case SZ_FEATURES: features = (const float*)d_in[i]; break;
            case SZ_MULTIQ:   multiQ   = (const float*)d_in[i]; break;
            case SZ_MULTIM:   multiM   = (const float*)d_in[i]; break;
            case SZ_NEAREST:  nearest  = (const int*)  d_in[i]; break;
            default: break;
        }
    }

    float* out_u = (float*)d_out;
    float* out_d = (float*)d_out + U_SIZE;

    k0_analyze<<<1, 1024>>>(multiM, multiQ);
    {
        int threads = 256, blocks = (BTNH + threads - 1) / threads;
        k1_compute_g<<<blocks, threads>>>(features, multiM);   // no-op when M diagonal
    }
    {
        int threads = 256, blocks = (BTNH + threads - 1) / threads;
        k2_w_deg<<<blocks, threads>>>(features, nearest, out_u);
    }
    {
        int threads = 256, blocks = (BTNH + threads - 1) / threads;
        k3_normalize<<<blocks, threads>>>(nearest, out_u);
    }
    {
        int threads = 256, blocks = (BRNH + threads - 1) / threads;
        k4_temporal<<<blocks, threads>>>(features, multiQ, out_d);
    }
}